// round 15
// baseline (speedup 1.0000x reference)
#include <cuda_runtime.h>
#include <cuda_fp16.h>
#include <math.h>
#include <stdint.h>

#define DIM      128
#define NCENT    30
#define DIME     158
#define N_NODES  50000
#define N_EDGES  800000
#define N_CONV   3
#define EVOCAB   500
#define LDA      132
#define TILE     128
#define NTHREADS 256
#define ETHR     384
#define NWARP    12
#define N_EUNITS (N_EDGES / 16)   // 50000
#define N_NUNITS (N_NODES / 16)   // 3125 (exact)

extern __shared__ __align__(1024) char smem_raw[];

__device__ __align__(256) float g_H[(size_t)N_NODES * DIM];
__device__ __align__(256) float g_NP[(size_t)N_NODES * DIM];
__device__ __align__(256) float g_T1[(size_t)N_CONV * 512 * DIM];

// ---------------------------------------------------------------------------
// helpers
// ---------------------------------------------------------------------------
__device__ __forceinline__ uint32_t pack_h2(float x, float y) {
    __half2 h = __floats2half2_rn(x, y);
    return *reinterpret_cast<uint32_t*>(&h);
}

__device__ __forceinline__ float tanh_fast(float x) {
    float ax = fabsf(x);
    float e = __expf(-2.0f * ax);
    float t = __fdividef(1.0f - e, 1.0f + e);
    return copysignf(t, x);
}

__device__ __forceinline__ void red_add_v2(float* p, float a, float b) {
    asm volatile("red.global.add.v2.f32 [%0], {%1, %2};"
                 :: "l"(p), "f"(a), "f"(b) : "memory");
}

// fp16 m16n8k16, fp32 accumulate
__device__ __forceinline__ void mma_f16(float c[4], const uint32_t a[4],
                                        uint32_t b0, uint32_t b1) {
    asm volatile(
        "mma.sync.aligned.m16n8k16.row.col.f32.f16.f16.f32 "
        "{%0,%1,%2,%3}, {%4,%5,%6,%7}, {%8,%9}, {%0,%1,%2,%3};"
        : "+f"(c[0]), "+f"(c[1]), "+f"(c[2]), "+f"(c[3])
        : "r"(a[0]), "r"(a[1]), "r"(a[2]), "r"(a[3]), "r"(b0), "r"(b1));
}

// Warp-independent fp16 GEMM: acc[16][4] += band[16r][K] * W[K][128c]
// band: uint32 words (k-pairs), row stride 68. Bw: word (k/2, n), stride 136.
template <int KSTEPS>   // KSTEPS = K/16
__device__ __forceinline__ void hgemm_h(const uint32_t* __restrict__ band,
                                        const uint32_t* __restrict__ Bw,
                                        int gid, int t4, float acc[16][4]) {
#pragma unroll 2
    for (int ks = 0; ks < KSTEPS; ++ks) {
        const int w0 = ks * 8 + t4;
        uint32_t a[4];
        a[0] = band[gid * 68 + w0];
        a[1] = band[(gid + 8) * 68 + w0];
        a[2] = band[gid * 68 + w0 + 4];
        a[3] = band[(gid + 8) * 68 + w0 + 4];
        const uint32_t* b0p = Bw + w0 * 136 + gid;
        const uint32_t* b1p = Bw + (w0 + 4) * 136 + gid;
#pragma unroll
        for (int nb = 0; nb < 16; ++nb)
            mma_f16(acc[nb], a, b0p[nb * 8], b1p[nb * 8]);
    }
}

// GEMM0 with register-computed fp16 rbf A fragments (K=32 -> 2 ksteps)
__device__ __forceinline__ float rbf_v(float d, int j) {
    if (j >= NCENT) return 0.f;
    float t = d - (10.0f / 29.0f) * (float)j;
    return __expf(-t * t * (29.0f / 10.0f));
}

__device__ __forceinline__ void hgemm0_rbf_h(const float d2[2],
                                             const uint32_t* __restrict__ WRw,
                                             int gid, int t4, float acc[16][4]) {
#pragma unroll
    for (int ks = 0; ks < 2; ++ks) {
        const int k = ks * 16 + 2 * t4;   // lower-k pair start
        uint32_t a[4];
        a[0] = pack_h2(rbf_v(d2[0], k),     rbf_v(d2[0], k + 1));
        a[1] = pack_h2(rbf_v(d2[1], k),     rbf_v(d2[1], k + 1));
        a[2] = pack_h2(rbf_v(d2[0], k + 8), rbf_v(d2[0], k + 9));
        a[3] = pack_h2(rbf_v(d2[1], k + 8), rbf_v(d2[1], k + 9));
        const int w0 = ks * 8 + t4;
        const uint32_t* b0p = WRw + w0 * 136 + gid;
        const uint32_t* b1p = WRw + (w0 + 4) * 136 + gid;
#pragma unroll
        for (int nb = 0; nb < 16; ++nb)
            mma_f16(acc[nb], a, b0p[nb * 8], b1p[nb * 8]);
    }
}

__device__ __forceinline__ void zacc_w(float acc[16][4]) {
#pragma unroll
    for (int n = 0; n < 16; ++n)
#pragma unroll
        for (int j = 0; j < 4; ++j) acc[n][j] = 0.f;
}

// stage 128x128 fp32 weight -> fp16 word layout (word w = (W[2w][n],W[2w+1][n]))
__device__ __forceinline__ void stage_Bh(uint32_t* dst, const float* __restrict__ W,
                                         int tid, int nthr) {
    for (int idx = tid; idx < 64 * 128; idx += nthr) {
        int w = idx >> 7, n = idx & 127;
        dst[w * 136 + n] = pack_h2(__ldg(&W[(2 * w) * DIM + n]),
                                   __ldg(&W[(2 * w + 1) * DIM + n]));
    }
}

// load 2 H rows (gid, gid+8 of unit) into fp16 band
__device__ __forceinline__ void load_h_band(uint32_t* band, int n0, int gid, int t4) {
#pragma unroll
    for (int h = 0; h < 2; ++h) {
        const float* hp = g_H + (size_t)(n0 + gid + 8 * h) * DIM;
        uint32_t* bp = band + (gid + 8 * h) * 68;
#pragma unroll
        for (int i = 0; i < 8; ++i) {
            const int c = t4 * 4 + i * 16;     // float index
            float4 v = *(const float4*)(hp + c);
            bp[(c >> 1)]     = pack_h2(v.x, v.y);
            bp[(c >> 1) + 1] = pack_h2(v.z, v.w);
        }
    }
}

// ---------------------------------------------------------------------------
// FFMA helpers (k_t1 only)
// ---------------------------------------------------------------------------
__device__ __forceinline__ void zero_acc8(float acc[8][8]) {
#pragma unroll
    for (int i = 0; i < 8; ++i)
#pragma unroll
        for (int j = 0; j < 8; ++j) acc[i][j] = 0.f;
}

template <int K, int KW, int LD>
__device__ __forceinline__ void gemm_frag4(const float* __restrict__ As,
                                           const float* __restrict__ W,
                                           int r0, int c0, float acc[8][8]) {
#pragma unroll 2
    for (int k = 0; k < K; k += 4) {
        float4 a4[8];
#pragma unroll
        for (int i = 0; i < 8; ++i) a4[i] = *(const float4*)&As[(r0 + i) * LD + k];
        const float* a = (const float*)a4;
#pragma unroll
        for (int kk = 0; kk < 4; ++kk) {
            int kq = k + kk;
            float w[8];
            if (K == KW || kq < KW) {
                float4 w0 = __ldg((const float4*)(W + kq * DIM + c0));
                float4 w1 = __ldg((const float4*)(W + kq * DIM + c0 + 4));
                w[0] = w0.x; w[1] = w0.y; w[2] = w0.z; w[3] = w0.w;
                w[4] = w1.x; w[5] = w1.y; w[6] = w1.z; w[7] = w1.w;
            } else {
#pragma unroll
                for (int j = 0; j < 8; ++j) w[j] = 0.f;
            }
#pragma unroll
            for (int i = 0; i < 8; ++i)
#pragma unroll
                for (int j = 0; j < 8; ++j)
                    acc[i][j] = fmaf(a[i * 4 + kk], w[j], acc[i][j]);
        }
    }
}

// ---------------------------------------------------------------------------
// small kernels
// ---------------------------------------------------------------------------
__global__ void k_zero(float* out, int n) {
    int i = blockIdx.x * blockDim.x + threadIdx.x;
    if (i < n) out[i] = 0.f;
}

__global__ void k_embed(const int* __restrict__ nt, const float* __restrict__ emb) {
    int idx = blockIdx.x * blockDim.x + threadIdx.x;
    if (idx < N_NODES * 32) {
        int n = idx >> 5, q = idx & 31;
        ((float4*)g_H)[(size_t)n * 32 + q] =
            __ldg(((const float4*)emb) + (size_t)nt[n] * 32 + q);
    }
}

__global__ __launch_bounds__(NTHREADS) void k_t1(const float* __restrict__ edge_emb,
                                                 const float* __restrict__ We1_all,
                                                 const float* __restrict__ be1_all) {
    float* As = (float*)smem_raw;
    const int tid = threadIdx.x;
    const int layer = blockIdx.y;
    const int t0b = blockIdx.x * TILE;
    const float* We1 = We1_all + (size_t)layer * DIME * DIM;
    const float* be1 = be1_all + (size_t)layer * DIM;
    float* T1 = g_T1 + (size_t)layer * 512 * DIM;

    for (int idx = tid; idx < TILE * 32; idx += NTHREADS) {
        int r = idx >> 5, q = idx & 31;
        int row = t0b + r;
        float4 v = make_float4(0.f, 0.f, 0.f, 0.f);
        if (row < EVOCAB) v = __ldg(((const float4*)edge_emb) + (size_t)row * 32 + q);
        *(float4*)&As[r * LDA + q * 4] = v;
    }
    __syncthreads();
    const int tr = tid >> 4, tc = tid & 15;
    const int r0 = tr * 8, c0 = tc * 8;
    float acc[8][8];
    zero_acc8(acc);
    gemm_frag4<DIM, DIM, LDA>(As, We1, r0, c0, acc);
    float4 b0 = __ldg((const float4*)(be1 + c0));
    float4 b1 = __ldg((const float4*)(be1 + c0 + 4));
    float bb[8] = {b0.x, b0.y, b0.z, b0.w, b1.x, b1.y, b1.z, b1.w};
#pragma unroll
    for (int i = 0; i < 8; ++i) {
        int row = t0b + r0 + i;
        if (row < EVOCAB) {
            float* tp = T1 + (size_t)row * DIM + c0;
            *(float4*)tp       = make_float4(acc[i][0] + bb[0], acc[i][1] + bb[1],
                                             acc[i][2] + bb[2], acc[i][3] + bb[3]);
            *(float4*)(tp + 4) = make_float4(acc[i][4] + bb[4], acc[i][5] + bb[5],
                                             acc[i][6] + bb[6], acc[i][7] + bb[7]);
        }
    }
}

// ---------------------------------------------------------------------------
// fp16 warp-independent node-path — 384 threads, 12 chains, zero barriers.
// smem bytes: A 12*16*68*4=52224 | W1 34816 @52224 | W2 34816 @87040 |
//             b1 512 @121856 | b2 512 @122368 -> 122880 B
// ---------------------------------------------------------------------------
#define NP_W1 52224
#define NP_W2 87040
#define NP_B1 121856
#define NP_B2 122368
#define NPSMEM 122880

__global__ __launch_bounds__(ETHR, 1) void k_nodepath_hmma(const float* __restrict__ Wn1,
                                                           const float* __restrict__ bn1,
                                                           const float* __restrict__ Wn2,
                                                           const float* __restrict__ bn2) {
    char* smb = smem_raw;
    uint32_t* W1w = (uint32_t*)(smb + NP_W1);
    uint32_t* W2w = (uint32_t*)(smb + NP_W2);
    float* sb1 = (float*)(smb + NP_B1);
    float* sb2 = (float*)(smb + NP_B2);

    const int tid = threadIdx.x;
    const int wid = tid >> 5, lane = tid & 31;
    const int gid = lane >> 2, t4 = lane & 3;

    stage_Bh(W1w, Wn1, tid, ETHR);
    stage_Bh(W2w, Wn2, tid, ETHR);
    if (tid < 128) { sb1[tid] = __ldg(&bn1[tid]); sb2[tid] = __ldg(&bn2[tid]); }
    __syncthreads();

    uint32_t* band = (uint32_t*)smb + wid * 16 * 68;
    float acc[16][4];

    for (int u = blockIdx.x * NWARP + wid; u < N_NUNITS; u += 148 * NWARP) {
        const int n0 = u * 16;
        load_h_band(band, n0, gid, t4);

        zacc_w(acc);
        hgemm_h<8>(band, W1w, gid, t4, acc);

        // relu(acc + bn1) -> fp16 band
#pragma unroll
        for (int h = 0; h < 2; ++h) {
            uint32_t* bp = band + (gid + 8 * h) * 68;
#pragma unroll
            for (int nb = 0; nb < 16; ++nb) {
                const int col = nb * 8 + t4 * 2;
                float2 bb = *(const float2*)(sb1 + col);
                bp[col >> 1] = pack_h2(fmaxf(acc[nb][2 * h + 0] + bb.x, 0.f),
                                       fmaxf(acc[nb][2 * h + 1] + bb.y, 0.f));
            }
        }

        zacc_w(acc);
        hgemm_h<8>(band, W2w, gid, t4, acc);

        // NP = acc + bn2 (fp32 out)
#pragma unroll
        for (int h = 0; h < 2; ++h) {
            float* np = g_NP + (size_t)(n0 + gid + 8 * h) * DIM;
#pragma unroll
            for (int nb = 0; nb < 16; ++nb) {
                const int col = nb * 8 + t4 * 2;
                float2 bb = *(const float2*)(sb2 + col);
                *(float2*)(np + col) = make_float2(acc[nb][2 * h + 0] + bb.x,
                                                   acc[nb][2 * h + 1] + bb.y);
            }
        }
    }
}

// ---------------------------------------------------------------------------
// fp16 warp-independent readout — dot straight from acc + shfl reduce.
// smem: A 52224 | W1 34816 @52224 | sb1 512 @87040 | sw2 512 @87552 -> 88064 B
// ---------------------------------------------------------------------------
#define RO_W1 52224
#define RO_B1 87040
#define RO_W2 87552
#define ROSMEM 88064

__global__ __launch_bounds__(ETHR, 1) void k_readout_hmma(const int* __restrict__ gids,
                                                          const float* __restrict__ Wr1,
                                                          const float* __restrict__ br1,
                                                          const float* __restrict__ Wr2,
                                                          const float* __restrict__ br2,
                                                          float* __restrict__ out) {
    char* smb = smem_raw;
    uint32_t* W1w = (uint32_t*)(smb + RO_W1);
    float* sb1 = (float*)(smb + RO_B1);
    float* sw2 = (float*)(smb + RO_W2);

    const int tid = threadIdx.x;
    const int wid = tid >> 5, lane = tid & 31;
    const int gid = lane >> 2, t4 = lane & 3;

    stage_Bh(W1w, Wr1, tid, ETHR);
    if (tid < 128) { sb1[tid] = __ldg(&br1[tid]); sw2[tid] = __ldg(&Wr2[tid]); }
    __syncthreads();
    const float b2v = __ldg(&br2[0]);

    uint32_t* band = (uint32_t*)smb + wid * 16 * 68;
    float acc[16][4];

    for (int u = blockIdx.x * NWARP + wid; u < N_NUNITS; u += 148 * NWARP) {
        const int n0 = u * 16;
        load_h_band(band, n0, gid, t4);

        zacc_w(acc);
        hgemm_h<8>(band, W1w, gid, t4, acc);

        float p[2] = {0.f, 0.f};
#pragma unroll
        for (int nb = 0; nb < 16; ++nb) {
            const int col = nb * 8 + t4 * 2;
            float2 bb = *(const float2*)(sb1 + col);
            float2 ww = *(const float2*)(sw2 + col);
#pragma unroll
            for (int h = 0; h < 2; ++h) {
                p[h] += fmaxf(acc[nb][2 * h + 0] + bb.x, 0.f) * ww.x
                      + fmaxf(acc[nb][2 * h + 1] + bb.y, 0.f) * ww.y;
            }
        }
#pragma unroll
        for (int h = 0; h < 2; ++h) {
            p[h] += __shfl_xor_sync(0xffffffff, p[h], 1);
            p[h] += __shfl_xor_sync(0xffffffff, p[h], 2);
        }
        if (t4 == 0) {
            atomicAdd(&out[__ldg(&gids[n0 + gid])], p[0] + b2v);
            atomicAdd(&out[__ldg(&gids[n0 + gid + 8])], p[1] + b2v);
        }
    }
}

// ---------------------------------------------------------------------------
// fp16 warp-independent edge kernel — 384 threads, 12 decoupled chains.
// smem bytes: A 52224 | W2 34816 @52224 | WC 34816 @87040 | WR 8704 @121856 |
//             be2 512 @130560 | bc 512 @131072 -> 131584 B
// ---------------------------------------------------------------------------
#define F_W2  52224
#define F_WC  87040
#define F_WR  121856
#define F_BE2 130560
#define F_BC  131072
#define ESMEM 131584

__global__ __launch_bounds__(ETHR, 1) void k_edge_hmma(const int* __restrict__ etype,
                                                       const int* __restrict__ esrc,
                                                       const int* __restrict__ edst,
                                                       const float* __restrict__ dist,
                                                       const float* __restrict__ We1rbf,
                                                       const float* __restrict__ We2,
                                                       const float* __restrict__ be2,
                                                       const float* __restrict__ Wc,
                                                       const float* __restrict__ bc,
                                                       int layer) {
    char* smb = smem_raw;
    uint32_t* W2w = (uint32_t*)(smb + F_W2);
    uint32_t* WCw = (uint32_t*)(smb + F_WC);
    uint32_t* WRw = (uint32_t*)(smb + F_WR);
    float* sbe2 = (float*)(smb + F_BE2);
    float* sbc  = (float*)(smb + F_BC);

    const int tid = threadIdx.x;
    const int wid = tid >> 5;
    const int lane = tid & 31;
    const int gid = lane >> 2;
    const int t4  = lane & 3;

    stage_Bh(W2w, We2, tid, ETHR);
    stage_Bh(WCw, Wc, tid, ETHR);
    // WR: K=32 -> 16 word rows; zero beyond NCENT
    for (int idx = tid; idx < 16 * 128; idx += ETHR) {
        int w = idx >> 7, n = idx & 127;
        int k0 = 2 * w, k1 = 2 * w + 1;
        float lo = (k0 < NCENT) ? __ldg(&We1rbf[k0 * DIM + n]) : 0.f;
        float hi = (k1 < NCENT) ? __ldg(&We1rbf[k1 * DIM + n]) : 0.f;
        WRw[w * 136 + n] = pack_h2(lo, hi);
    }
    if (tid < 128) { sbe2[tid] = __ldg(&be2[tid]); sbc[tid] = __ldg(&bc[tid]); }
    const float* T1 = g_T1 + (size_t)layer * 512 * DIM;
    __syncthreads();

    uint32_t* band = (uint32_t*)smb + wid * 16 * 68;

    float acc[16][4];
    float2 pf[2][16];

    for (int u = blockIdx.x * NWARP + wid; u < N_EUNITS; u += 148 * NWARP) {
        const int e0 = u * 16;

        float d2[2];
        d2[0] = __ldg(&dist[e0 + gid]);
        d2[1] = __ldg(&dist[e0 + gid + 8]);

        // prefetch T1[type] (overlaps GEMM0)
#pragma unroll
        for (int h = 0; h < 2; ++h) {
            const int ty = __ldg(&etype[e0 + gid + 8 * h]);
            const float* t1p = T1 + (size_t)ty * DIM + t4 * 2;
#pragma unroll
            for (int nb = 0; nb < 16; ++nb)
                pf[h][nb] = __ldg((const float2*)(t1p + nb * 8));
        }

        // GEMM0: rbf (registers, fp16) @ We1rbf
        zacc_w(acc);
        hgemm0_rbf_h(d2, WRw, gid, t4, acc);

        // epi0: P1 = fp16(relu(acc + T1)) -> band
#pragma unroll
        for (int h = 0; h < 2; ++h) {
            uint32_t* bp = band + (gid + 8 * h) * 68;
#pragma unroll
            for (int nb = 0; nb < 16; ++nb) {
                const int col = nb * 8 + t4 * 2;
                bp[col >> 1] = pack_h2(fmaxf(acc[nb][2 * h + 0] + pf[h][nb].x, 0.f),
                                       fmaxf(acc[nb][2 * h + 1] + pf[h][nb].y, 0.f));
            }
        }

        // prefetch NP[src] (overlaps GEMM1)
#pragma unroll
        for (int h = 0; h < 2; ++h) {
            const int sr = __ldg(&esrc[e0 + gid + 8 * h]);
            const float* npp = g_NP + (size_t)sr * DIM + t4 * 2;
#pragma unroll
            for (int nb = 0; nb < 16; ++nb)
                pf[h][nb] = __ldg((const float2*)(npp + nb * 8));
        }

        // GEMM1: P1 @ We2
        zacc_w(acc);
        hgemm_h<8>(band, W2w, gid, t4, acc);

        // epi1: P2 = fp16((acc + be2) * NP) -> band
#pragma unroll
        for (int h = 0; h < 2; ++h) {
            uint32_t* bp = band + (gid + 8 * h) * 68;
#pragma unroll
            for (int nb = 0; nb < 16; ++nb) {
                const int col = nb * 8 + t4 * 2;
                float2 bb = *(const float2*)(sbe2 + col);
                bp[col >> 1] = pack_h2((acc[nb][2 * h + 0] + bb.x) * pf[h][nb].x,
                                       (acc[nb][2 * h + 1] + bb.y) * pf[h][nb].y);
            }
        }

        // GEMM2: P2 @ Wc
        zacc_w(acc);
        hgemm_h<8>(band, WCw, gid, t4, acc);

        // epi2: m = tanh(acc + bc); H[dst] += m
#pragma unroll
        for (int h = 0; h < 2; ++h) {
            const int ds = __ldg(&edst[e0 + gid + 8 * h]);
            float* hp = g_H + (size_t)ds * DIM;
#pragma unroll
            for (int nb = 0; nb < 16; ++nb) {
                const int col = nb * 8 + t4 * 2;
                float2 bb = *(const float2*)(sbc + col);
                float m0 = tanh_fast(acc[nb][2 * h + 0] + bb.x);
                float m1 = tanh_fast(acc[nb][2 * h + 1] + bb.y);
                red_add_v2(hp + col, m0, m1);
            }
        }
    }
}

// ---------------------------------------------------------------------------
// launch
// ---------------------------------------------------------------------------
extern "C" void kernel_launch(void* const* d_in, const int* in_sizes, int n_in,
                              void* d_out, int out_size) {
    const int wb = n_in - 16;
    const int*   node_types = (const int*)d_in[0];
    const int*   edge_types = (const int*)d_in[1];
    const int*   src        = (const int*)d_in[2];
    const int*   dst        = (const int*)d_in[3];
    const int*   graph_ids  = (const int*)d_in[4];
    const float* distances  = (const float*)d_in[5];
    const float* node_emb = (const float*)d_in[wb + 0];
    const float* edge_emb = (const float*)d_in[wb + 1];
    const float* Wn1 = (const float*)d_in[wb + 2];
    const float* bn1 = (const float*)d_in[wb + 3];
    const float* Wn2 = (const float*)d_in[wb + 4];
    const float* bn2 = (const float*)d_in[wb + 5];
    const float* We1 = (const float*)d_in[wb + 6];
    const float* be1 = (const float*)d_in[wb + 7];
    const float* We2 = (const float*)d_in[wb + 8];
    const float* be2 = (const float*)d_in[wb + 9];
    const float* Wc  = (const float*)d_in[wb + 10];
    const float* bc  = (const float*)d_in[wb + 11];
    const float* Wr1 = (const float*)d_in[wb + 12];
    const float* br1 = (const float*)d_in[wb + 13];
    const float* Wr2 = (const float*)d_in[wb + 14];
    const float* br2 = (const float*)d_in[wb + 15];
    float* out = (float*)d_out;

    const int TSM = TILE * LDA * 4;

    cudaFuncSetAttribute(k_edge_hmma,     cudaFuncAttributeMaxDynamicSharedMemorySize, ESMEM);
    cudaFuncSetAttribute(k_nodepath_hmma, cudaFuncAttributeMaxDynamicSharedMemorySize, NPSMEM);
    cudaFuncSetAttribute(k_readout_hmma,  cudaFuncAttributeMaxDynamicSharedMemorySize, ROSMEM);
    cudaFuncSetAttribute(k_t1,            cudaFuncAttributeMaxDynamicSharedMemorySize, TSM);

    k_zero<<<1, 128>>>(out, out_size);
    k_embed<<<(N_NODES * 32 + 255) / 256, 256>>>(node_types, node_emb);
    k_t1<<<dim3(4, 3), NTHREADS, TSM>>>(edge_emb, We1, be1);

    for (int i = 0; i < N_CONV; ++i) {
        k_nodepath_hmma<<<148, ETHR, NPSMEM>>>(
            Wn1 + (size_t)i * DIM * DIM, bn1 + (size_t)i * DIM,
            Wn2 + (size_t)i * DIM * DIM, bn2 + (size_t)i * DIM);
        k_edge_hmma<<<148, ETHR, ESMEM>>>(
            edge_types, src, dst, distances,
            We1 + (size_t)i * DIME * DIM + (size_t)DIM * DIM,
            We2 + (size_t)i * DIM * DIM, be2 + (size_t)i * DIM,
            Wc + (size_t)i * DIM * DIM, bc + (size_t)i * DIM, i);
    }

    k_readout_hmma<<<148, ETHR, ROSMEM>>>(
        graph_ids, Wr1, br1, Wr2, br2, out);
}

// round 16
// speedup vs baseline: 1.0439x; 1.0439x over previous
#include <cuda_runtime.h>
#include <math.h>
#include <stdint.h>

#define DIM      128
#define NCENT    30
#define DIME     158
#define N_NODES  50000
#define N_EDGES  800000
#define N_CONV   3
#define EVOCAB   500
#define TILE     128
#define NTHREADS 256
#define N_EUNITS (N_EDGES / 16)   // 50000
#define N_NUNITS (N_NODES / 16)   // 3125 (exact)

extern __shared__ __align__(1024) char smem_raw[];

__device__ __align__(256) float g_H[(size_t)N_NODES * DIM];
__device__ __align__(256) float g_NP[(size_t)N_NODES * DIM];
__device__ __align__(256) float g_T1[(size_t)N_CONV * 512 * DIM];

// ---------------------------------------------------------------------------
// helpers
// ---------------------------------------------------------------------------
__device__ __forceinline__ float to_tf32(float x) {
    float r; asm("cvt.rna.tf32.f32 %0, %1;" : "=f"(r) : "f"(x)); return r;
}

__device__ __forceinline__ float tanh_fast(float x) {
    float ax = fabsf(x);
    float e = __expf(-2.0f * ax);
    float t = __fdividef(1.0f - e, 1.0f + e);
    return copysignf(t, x);
}

__device__ __forceinline__ void red_add_v2(float* p, float a, float b) {
    asm volatile("red.global.add.v2.f32 [%0], {%1, %2};"
                 :: "l"(p), "f"(a), "f"(b) : "memory");
}

__device__ __forceinline__ void mma1688(float c[4], const uint32_t a[4],
                                        uint32_t b0, uint32_t b1) {
    asm volatile(
        "mma.sync.aligned.m16n8k8.row.col.f32.tf32.tf32.f32 "
        "{%0,%1,%2,%3}, {%4,%5,%6,%7}, {%8,%9}, {%0,%1,%2,%3};"
        : "+f"(c[0]), "+f"(c[1]), "+f"(c[2]), "+f"(c[3])
        : "r"(a[0]), "r"(a[1]), "r"(a[2]), "r"(a[3]), "r"(b0), "r"(b1));
}

// Warp-independent GEMM: acc[16][4] += band[16 rows][K] * W[K][128 cols]
// band: 16x132 floats (warp-private). B2 layout: float2 row (ks*4+t4),
// stride 132 float2; (.x,.y) = W[k], W[k+4].
template <int KSTEPS>
__device__ __forceinline__ void hgemm_w(const uint32_t* __restrict__ band,
                                        const float2* __restrict__ B2,
                                        int gid, int t4, float acc[16][4]) {
#pragma unroll 2
    for (int ks = 0; ks < KSTEPS; ++ks) {
        const int k0 = ks * 8;
        uint32_t a[4];
        a[0] = band[gid * 132 + k0 + t4];
        a[1] = band[(gid + 8) * 132 + k0 + t4];
        a[2] = band[gid * 132 + k0 + t4 + 4];
        a[3] = band[(gid + 8) * 132 + k0 + t4 + 4];
        const float2* brow = B2 + (ks * 4 + t4) * 132 + gid;
#pragma unroll
        for (int nb = 0; nb < 16; ++nb) {
            float2 b = brow[nb * 8];
            mma1688(acc[nb], a, __float_as_uint(b.x), __float_as_uint(b.y));
        }
    }
}

// GEMM0 with register-resident rbf A fragments (no smem A traffic).
__device__ __forceinline__ void hgemm0_rbf_w(const float d2[2],
                                             const float2* __restrict__ WR2,
                                             int gid, int t4, float acc[16][4]) {
#pragma unroll
    for (int ks = 0; ks < 4; ++ks) {
        uint32_t a[4];
        const int j0 = ks * 8 + t4;       // <= 27
        const int j1 = j0 + 4;            // may be >= NCENT
        const float c0 = (10.0f / 29.0f) * (float)j0;
        const float c1 = (10.0f / 29.0f) * (float)j1;
#pragma unroll
        for (int h = 0; h < 2; ++h) {
            const float d = d2[h];
            float t0 = d - c0;
            float v0 = to_tf32(__expf(-t0 * t0 * (29.0f / 10.0f)));
            float v1 = 0.f;
            if (j1 < NCENT) {
                float t1 = d - c1;
                v1 = to_tf32(__expf(-t1 * t1 * (29.0f / 10.0f)));
            }
            a[h]     = __float_as_uint(v0);
            a[h + 2] = __float_as_uint(v1);
        }
        const float2* brow = WR2 + (ks * 4 + t4) * 132 + gid;
#pragma unroll
        for (int nb = 0; nb < 16; ++nb) {
            float2 b = brow[nb * 8];
            mma1688(acc[nb], a, __float_as_uint(b.x), __float_as_uint(b.y));
        }
    }
}

__device__ __forceinline__ void zacc_w(float acc[16][4]) {
#pragma unroll
    for (int n = 0; n < 16; ++n)
#pragma unroll
        for (int j = 0; j < 4; ++j) acc[n][j] = 0.f;
}

// stage a 128x128 weight into B2 layout (tf32)
__device__ __forceinline__ void stage_B2(float2* dst, const float* __restrict__ W, int tid) {
    for (int idx = tid; idx < 64 * 128; idx += NTHREADS) {
        int row = idx >> 7, n = idx & 127;
        int klo = (row >> 2) * 8 + (row & 3);
        dst[row * 132 + n] = make_float2(to_tf32(__ldg(&W[klo * DIM + n])),
                                         to_tf32(__ldg(&W[(klo + 4) * DIM + n])));
    }
}

// load 2 H rows (gid, gid+8 of unit) into warp band as tf32
__device__ __forceinline__ void load_h_band(float* bandf, int n0, int gid, int t4) {
#pragma unroll
    for (int h = 0; h < 2; ++h) {
        const float* hp = g_H + (size_t)(n0 + gid + 8 * h) * DIM;
        float* bp = bandf + (gid + 8 * h) * 132;
#pragma unroll
        for (int i = 0; i < 8; ++i) {
            const int c = t4 * 4 + i * 16;
            float4 v = *(const float4*)(hp + c);
            v.x = to_tf32(v.x); v.y = to_tf32(v.y);
            v.z = to_tf32(v.z); v.w = to_tf32(v.w);
            *(float4*)(bp + c) = v;
        }
    }
}

// ---------------------------------------------------------------------------
// small kernels
// ---------------------------------------------------------------------------
__global__ void k_zero(float* out, int n) {
    int i = blockIdx.x * blockDim.x + threadIdx.x;
    if (i < n) out[i] = 0.f;
}

__global__ void k_embed(const int* __restrict__ nt, const float* __restrict__ emb) {
    int idx = blockIdx.x * blockDim.x + threadIdx.x;
    if (idx < N_NODES * 32) {
        int n = idx >> 5, q = idx & 31;
        ((float4*)g_H)[(size_t)n * 32 + q] =
            __ldg(((const float4*)emb) + (size_t)nt[n] * 32 + q);
    }
}

// ---------------------------------------------------------------------------
// HMMA warp-unit t1: T1[L][t] = edge_emb[t] @ We1[L][:128] + be1[L]
// grid (4, 3): blockIdx.x*8+wid = unit (16 type rows), blockIdx.y = layer.
// smem floats: band 16896 | W 16896 -> 135168 B
// ---------------------------------------------------------------------------
#define T1_W 16896
#define T1SMEM 135168

__global__ __launch_bounds__(NTHREADS, 1) void k_t1_hmma(const float* __restrict__ edge_emb,
                                                         const float* __restrict__ We1_all,
                                                         const float* __restrict__ be1_all) {
    float* smf = (float*)smem_raw;
    float2* Ww = (float2*)(smf + T1_W);

    const int tid = threadIdx.x;
    const int wid = tid >> 5, lane = tid & 31;
    const int gid = lane >> 2, t4 = lane & 3;
    const int layer = blockIdx.y;
    const float* We1 = We1_all + (size_t)layer * DIME * DIM;
    const float* be1 = be1_all + (size_t)layer * DIM;
    float* T1 = g_T1 + (size_t)layer * 512 * DIM;

    stage_B2(Ww, We1, tid);
    __syncthreads();

    float* bandf = smf + wid * 16 * 132;
    uint32_t* band = (uint32_t*)bandf;
    const int t0 = (blockIdx.x * 8 + wid) * 16;

    // load band rows (guarded)
#pragma unroll
    for (int h = 0; h < 2; ++h) {
        const int row = t0 + gid + 8 * h;
        float* bp = bandf + (gid + 8 * h) * 132;
        if (row < EVOCAB) {
            const float* ep = edge_emb + (size_t)row * DIM;
#pragma unroll
            for (int i = 0; i < 8; ++i) {
                const int c = t4 * 4 + i * 16;
                float4 v = __ldg((const float4*)(ep + c));
                v.x = to_tf32(v.x); v.y = to_tf32(v.y);
                v.z = to_tf32(v.z); v.w = to_tf32(v.w);
                *(float4*)(bp + c) = v;
            }
        } else {
#pragma unroll
            for (int i = 0; i < 8; ++i)
                *(float4*)(bp + t4 * 4 + i * 16) = make_float4(0.f, 0.f, 0.f, 0.f);
        }
    }

    float acc[16][4];
    zacc_w(acc);
    hgemm_w<16>(band, Ww, gid, t4, acc);

#pragma unroll
    for (int h = 0; h < 2; ++h) {
        const int row = t0 + gid + 8 * h;
        if (row < EVOCAB) {
            float* tp = T1 + (size_t)row * DIM;
#pragma unroll
            for (int nb = 0; nb < 16; ++nb) {
                const int col = nb * 8 + t4 * 2;
                float2 bb = __ldg((const float2*)(be1 + col));
                *(float2*)(tp + col) = make_float2(acc[nb][2 * h + 0] + bb.x,
                                                   acc[nb][2 * h + 1] + bb.y);
            }
        }
    }
}

// ---------------------------------------------------------------------------
// Warp-independent HMMA node-path: zero barriers in main loop.
// smem floats: As 16896 | W1 16896 | W2 16896 | sb1 128 | sb2 128 -> 203776 B
// ---------------------------------------------------------------------------
#define NP_W1 16896
#define NP_W2 33792
#define NP_B1 50688
#define NP_B2 50816
#define NPSMEM 203776

__global__ __launch_bounds__(NTHREADS, 1) void k_nodepath_hmma(const float* __restrict__ Wn1,
                                                               const float* __restrict__ bn1,
                                                               const float* __restrict__ Wn2,
                                                               const float* __restrict__ bn2) {
    float* smf = (float*)smem_raw;
    float2* W1_2 = (float2*)(smf + NP_W1);
    float2* W2_2 = (float2*)(smf + NP_W2);
    float* sb1 = smf + NP_B1;
    float* sb2 = smf + NP_B2;

    const int tid = threadIdx.x;
    const int wid = tid >> 5, lane = tid & 31;
    const int gid = lane >> 2, t4 = lane & 3;

    stage_B2(W1_2, Wn1, tid);
    stage_B2(W2_2, Wn2, tid);
    if (tid < 128) { sb1[tid] = __ldg(&bn1[tid]); sb2[tid] = __ldg(&bn2[tid]); }
    __syncthreads();

    float* bandf = smf + wid * 16 * 132;
    uint32_t* band = (uint32_t*)bandf;
    float acc[16][4];

    for (int u = blockIdx.x * 8 + wid; u < N_NUNITS; u += 148 * 8) {
        const int n0 = u * 16;
        load_h_band(bandf, n0, gid, t4);

        zacc_w(acc);
        hgemm_w<16>(band, W1_2, gid, t4, acc);

        // relu(acc + bn1) -> tf32 -> band
#pragma unroll
        for (int h = 0; h < 2; ++h) {
            float* bp = bandf + (gid + 8 * h) * 132;
#pragma unroll
            for (int nb = 0; nb < 16; ++nb) {
                const int col = nb * 8 + t4 * 2;
                float2 bb = *(const float2*)(sb1 + col);
                float v0 = to_tf32(fmaxf(acc[nb][2 * h + 0] + bb.x, 0.f));
                float v1 = to_tf32(fmaxf(acc[nb][2 * h + 1] + bb.y, 0.f));
                *(float2*)(bp + col) = make_float2(v0, v1);
            }
        }

        zacc_w(acc);
        hgemm_w<16>(band, W2_2, gid, t4, acc);

        // NP = acc + bn2
#pragma unroll
        for (int h = 0; h < 2; ++h) {
            float* np = g_NP + (size_t)(n0 + gid + 8 * h) * DIM;
#pragma unroll
            for (int nb = 0; nb < 16; ++nb) {
                const int col = nb * 8 + t4 * 2;
                float2 bb = *(const float2*)(sb2 + col);
                *(float2*)(np + col) = make_float2(acc[nb][2 * h + 0] + bb.x,
                                                   acc[nb][2 * h + 1] + bb.y);
            }
        }
    }
}

// ---------------------------------------------------------------------------
// Warp-independent HMMA readout: dot computed straight from acc + shfl reduce.
// smem floats: As 16896 | W1 16896 | sb1 128 | sw2 128 -> 136192 B
// ---------------------------------------------------------------------------
#define RO_W1 16896
#define RO_B1 33792
#define RO_W2 33920
#define ROSMEM 136192

__global__ __launch_bounds__(NTHREADS, 1) void k_readout_hmma(const int* __restrict__ gids,
                                                              const float* __restrict__ Wr1,
                                                              const float* __restrict__ br1,
                                                              const float* __restrict__ Wr2,
                                                              const float* __restrict__ br2,
                                                              float* __restrict__ out) {
    float* smf = (float*)smem_raw;
    float2* W1_2 = (float2*)(smf + RO_W1);
    float* sb1 = smf + RO_B1;
    float* sw2 = smf + RO_W2;

    const int tid = threadIdx.x;
    const int wid = tid >> 5, lane = tid & 31;
    const int gid = lane >> 2, t4 = lane & 3;

    stage_B2(W1_2, Wr1, tid);
    if (tid < 128) { sb1[tid] = __ldg(&br1[tid]); sw2[tid] = __ldg(&Wr2[tid]); }
    __syncthreads();
    const float b2v = __ldg(&br2[0]);

    float* bandf = smf + wid * 16 * 132;
    uint32_t* band = (uint32_t*)bandf;
    float acc[16][4];

    for (int u = blockIdx.x * 8 + wid; u < N_NUNITS; u += 148 * 8) {
        const int n0 = u * 16;
        load_h_band(bandf, n0, gid, t4);

        zacc_w(acc);
        hgemm_w<16>(band, W1_2, gid, t4, acc);

        float p[2] = {0.f, 0.f};
#pragma unroll
        for (int nb = 0; nb < 16; ++nb) {
            const int col = nb * 8 + t4 * 2;
            float2 bb = *(const float2*)(sb1 + col);
            float2 ww = *(const float2*)(sw2 + col);
#pragma unroll
            for (int h = 0; h < 2; ++h) {
                p[h] += fmaxf(acc[nb][2 * h + 0] + bb.x, 0.f) * ww.x
                      + fmaxf(acc[nb][2 * h + 1] + bb.y, 0.f) * ww.y;
            }
        }
#pragma unroll
        for (int h = 0; h < 2; ++h) {
            p[h] += __shfl_xor_sync(0xffffffff, p[h], 1);
            p[h] += __shfl_xor_sync(0xffffffff, p[h], 2);
        }
        if (t4 == 0) {
            atomicAdd(&out[__ldg(&gids[n0 + gid])], p[0] + b2v);
            atomicAdd(&out[__ldg(&gids[n0 + gid + 8])], p[1] + b2v);
        }
    }
}

// ---------------------------------------------------------------------------
// Warp-independent tf32 edge kernel — 8 decoupled chains, zero barriers,
// cross-unit software pipelining: next unit's indices + T1 rows prefetched
// before GEMM2 so the T1 gather hides behind GEMM2+epi2 (~5k cyc).
// smem floats: As 16896 | W2 16896 | WC 16896 | WR 4224 | sbe2 128 | sbc 128
//   -> 55168 floats = 220672 B
// ---------------------------------------------------------------------------
#define F_W2  16896
#define F_WC  33792
#define F_WR  50688
#define F_BE2 54912
#define F_BC  55040
#define ESMEM 220672

__global__ __launch_bounds__(NTHREADS, 1) void k_edge_hmma(const int* __restrict__ etype,
                                                           const int* __restrict__ esrc,
                                                           const int* __restrict__ edst,
                                                           const float* __restrict__ dist,
                                                           const float* __restrict__ We1rbf,
                                                           const float* __restrict__ We2,
                                                           const float* __restrict__ be2,
                                                           const float* __restrict__ Wc,
                                                           const float* __restrict__ bc,
                                                           int layer) {
    float* smf = (float*)smem_raw;
    float2* W2_2 = (float2*)(smf + F_W2);
    float2* WC_2 = (float2*)(smf + F_WC);
    float2* WR_2 = (float2*)(smf + F_WR);
    float* sbe2 = smf + F_BE2;
    float* sbc  = smf + F_BC;

    const int tid = threadIdx.x;
    const int wid = tid >> 5;
    const int lane = tid & 31;
    const int gid = lane >> 2;
    const int t4  = lane & 3;

    stage_B2(W2_2, We2, tid);
    stage_B2(WC_2, Wc, tid);
    for (int idx = tid; idx < 16 * 128; idx += NTHREADS) {
        int row = idx >> 7, n = idx & 127;
        int klo = (row >> 2) * 8 + (row & 3);
        int khi = klo + 4;
        float lo = to_tf32(__ldg(&We1rbf[klo * DIM + n]));
        float hi = (khi < NCENT) ? to_tf32(__ldg(&We1rbf[khi * DIM + n])) : 0.f;
        WR_2[row * 132 + n] = make_float2(lo, hi);
    }
    if (tid < 128) { sbe2[tid] = __ldg(&be2[tid]); sbc[tid] = __ldg(&bc[tid]); }
    const float* T1 = g_T1 + (size_t)layer * 512 * DIM;
    __syncthreads();

    float* bandf = smf + wid * 16 * 132;
    uint32_t* band = (uint32_t*)bandf;

    float acc[16][4];
    float2 pf[2][16];

    const int stride = 148 * 8;
    int u = blockIdx.x * 8 + wid;    // every warp has work (1184 << 50000)

    // ---- prologue: scalars + T1 prefetch for first unit ----
    int e0 = u * 16;
    float d2[2];
    int sr[2], ds[2];
    d2[0] = __ldg(&dist[e0 + gid]);
    d2[1] = __ldg(&dist[e0 + gid + 8]);
    sr[0] = __ldg(&esrc[e0 + gid]);
    sr[1] = __ldg(&esrc[e0 + gid + 8]);
    ds[0] = __ldg(&edst[e0 + gid]);
    ds[1] = __ldg(&edst[e0 + gid + 8]);
#pragma unroll
    for (int h = 0; h < 2; ++h) {
        const int ty = __ldg(&etype[e0 + gid + 8 * h]);
        const float* t1p = T1 + (size_t)ty * DIM + t4 * 2;
#pragma unroll
        for (int nb = 0; nb < 16; ++nb)
            pf[h][nb] = __ldg((const float2*)(t1p + nb * 8));
    }

    while (true) {
        // GEMM0: rbf (registers) @ We1rbf
        zacc_w(acc);
        hgemm0_rbf_w(d2, WR_2, gid, t4, acc);

        // epi0: P1 = tf32(relu(acc + T1)) -> band   (pf = T1 of current unit)
#pragma unroll
        for (int h = 0; h < 2; ++h) {
            float* bp = bandf + (gid + 8 * h) * 132;
#pragma unroll
            for (int nb = 0; nb < 16; ++nb) {
                const int col = nb * 8 + t4 * 2;
                float v0 = to_tf32(fmaxf(acc[nb][2 * h + 0] + pf[h][nb].x, 0.f));
                float v1 = to_tf32(fmaxf(acc[nb][2 * h + 1] + pf[h][nb].y, 0.f));
                *(float2*)(bp + col) = make_float2(v0, v1);
            }
        }

        // prefetch NP[src] (hides behind GEMM1)
#pragma unroll
        for (int h = 0; h < 2; ++h) {
            const float* npp = g_NP + (size_t)sr[h] * DIM + t4 * 2;
#pragma unroll
            for (int nb = 0; nb < 16; ++nb)
                pf[h][nb] = __ldg((const float2*)(npp + nb * 8));
        }

        // GEMM1: P1 @ We2
        zacc_w(acc);
        hgemm_w<16>(band, W2_2, gid, t4, acc);

        // epi1: P2 = tf32((acc + be2) * NP) -> band
#pragma unroll
        for (int h = 0; h < 2; ++h) {
            float* bp = bandf + (gid + 8 * h) * 132;
#pragma unroll
            for (int nb = 0; nb < 16; ++nb) {
                const int col = nb * 8 + t4 * 2;
                float2 bb = *(const float2*)(sbe2 + col);
                float v0 = to_tf32((acc[nb][2 * h + 0] + bb.x) * pf[h][nb].x);
                float v1 = to_tf32((acc[nb][2 * h + 1] + bb.y) * pf[h][nb].y);
                *(float2*)(bp + col) = make_float2(v0, v1);
            }
        }

        // ---- next-unit scalar loads + T1 prefetch (hide behind GEMM2+epi2) --
        const int un = u + stride;
        const bool more = (un < N_EUNITS);
        float d2n[2];
        int srn[2], dsn[2];
        if (more) {
            const int en = un * 16;
            d2n[0] = __ldg(&dist[en + gid]);
            d2n[1] = __ldg(&dist[en + gid + 8]);
            srn[0] = __ldg(&esrc[en + gid]);
            srn[1] = __ldg(&esrc[en + gid + 8]);
            dsn[0] = __ldg(&edst[en + gid]);
            dsn[1] = __ldg(&edst[en + gid + 8]);
#pragma unroll
            for (int h = 0; h < 2; ++h) {
                const int ty = __ldg(&etype[en + gid + 8 * h]);
                const float* t1p = T1 + (size_t)ty * DIM + t4 * 2;
#pragma unroll
                for (int nb = 0; nb < 16; ++nb)
                    pf[h][nb] = __ldg((const float2*)(t1p + nb * 8));
            }
        }

        // GEMM2: P2 @ Wc
        zacc_w(acc);
        hgemm_w<16>(band, WC_2, gid, t4, acc);

        // epi2: m = tanh(acc + bc); H[dst] += m
#pragma unroll
        for (int h = 0; h < 2; ++h) {
            float* hp = g_H + (size_t)ds[h] * DIM;
#pragma unroll
            for (int nb = 0; nb < 16; ++nb) {
                const int col = nb * 8 + t4 * 2;
                float2 bb = *(const float2*)(sbc + col);
                float m0 = tanh_fast(acc[nb][2 * h + 0] + bb.x);
                float m1 = tanh_fast(acc[nb][2 * h + 1] + bb.y);
                red_add_v2(hp + col, m0, m1);
            }
        }

        if (!more) break;
        u = un;
        d2[0] = d2n[0]; d2[1] = d2n[1];
        sr[0] = srn[0]; sr[1] = srn[1];
        ds[0] = dsn[0]; ds[1] = dsn[1];
    }
}

// ---------------------------------------------------------------------------
// launch
// ---------------------------------------------------------------------------
extern "C" void kernel_launch(void* const* d_in, const int* in_sizes, int n_in,
                              void* d_out, int out_size) {
    const int wb = n_in - 16;
    const int*   node_types = (const int*)d_in[0];
    const int*   edge_types = (const int*)d_in[1];
    const int*   src        = (const int*)d_in[2];
    const int*   dst        = (const int*)d_in[3];
    const int*   graph_ids  = (const int*)d_in[4];
    const float* distances  = (const float*)d_in[5];
    const float* node_emb = (const float*)d_in[wb + 0];
    const float* edge_emb = (const float*)d_in[wb + 1];
    const float* Wn1 = (const float*)d_in[wb + 2];
    const float* bn1 = (const float*)d_in[wb + 3];
    const float* Wn2 = (const float*)d_in[wb + 4];
    const float* bn2 = (const float*)d_in[wb + 5];
    const float* We1 = (const float*)d_in[wb + 6];
    const float* be1 = (const float*)d_in[wb + 7];
    const float* We2 = (const float*)d_in[wb + 8];
    const float* be2 = (const float*)d_in[wb + 9];
    const float* Wc  = (const float*)d_in[wb + 10];
    const float* bc  = (const float*)d_in[wb + 11];
    const float* Wr1 = (const float*)d_in[wb + 12];
    const float* br1 = (const float*)d_in[wb + 13];
    const float* Wr2 = (const float*)d_in[wb + 14];
    const float* br2 = (const float*)d_in[wb + 15];
    float* out = (float*)d_out;

    cudaFuncSetAttribute(k_edge_hmma,     cudaFuncAttributeMaxDynamicSharedMemorySize, ESMEM);
    cudaFuncSetAttribute(k_nodepath_hmma, cudaFuncAttributeMaxDynamicSharedMemorySize, NPSMEM);
    cudaFuncSetAttribute(k_readout_hmma,  cudaFuncAttributeMaxDynamicSharedMemorySize, ROSMEM);
    cudaFuncSetAttribute(k_t1_hmma,       cudaFuncAttributeMaxDynamicSharedMemorySize, T1SMEM);

    k_zero<<<1, 128>>>(out, out_size);
    k_embed<<<(N_NODES * 32 + 255) / 256, 256>>>(node_types, node_emb);
    k_t1_hmma<<<dim3(4, 3), NTHREADS, T1SMEM>>>(edge_emb, We1, be1);

    for (int i = 0; i < N_CONV; ++i) {
        k_nodepath_hmma<<<148, NTHREADS, NPSMEM>>>(
            Wn1 + (size_t)i * DIM * DIM, bn1 + (size_t)i * DIM,
            Wn2 + (size_t)i * DIM * DIM, bn2 + (size_t)i * DIM);
        k_edge_hmma<<<148, NTHREADS, ESMEM>>>(
            edge_types, src, dst, distances,
            We1 + (size_t)i * DIME * DIM + (size_t)DIM * DIM,
            We2 + (size_t)i * DIM * DIM, be2 + (size_t)i * DIM,
            Wc + (size_t)i * DIM * DIM, bc + (size_t)i * DIM, i);
    }

    k_readout_hmma<<<148, NTHREADS, ROSMEM>>>(
        graph_ids, Wr1, br1, Wr2, br2, out);
}